// round 14
// baseline (speedup 1.0000x reference)
#include <cuda_runtime.h>
#include <cuda_bf16.h>
#include <cuda_fp16.h>
#include <stdint.h>

// =====================================================================
// PatchNCELoss: loss[r] = lse_c( inv_t * q[r]·k[c] ) - inv_t * q[r]·k[r]
// Q,K: [8192, 256] fp32.  bf16 hi/lo split -> 3 GEMM products fused into
// one mma.sync mainloop + per-tile log2-domain softmax partials.
// R14: epilogue exp2 via packed ex2.approx.f16x2 (2 exps / MUFU op,
// fp16x2 accumulation) -> MUFU pressure halved.  Keeps R13 stagger,
// pairwise sync, persistent scheduling, dynamic SM count.
// =====================================================================

#define N_TOT 8192
#define DDIM  256
#define INV_T_F     14.285714285714286f
#define QSCALE_F    20.609929155556627f   /* inv_t * log2(e) */
#define LN2_F       0.6931471805599453f

#define COLTILES  32                       // 256-col tiles
#define UNITS     (64 * COLTILES)          // 2048
#define CHUNKS_PT 8                        // 4 k64 x {Kh, Kl}
#define NSLOT     128                      // 32 coltiles x 4 warp_n

// ---- device scratch ----
__device__ __align__(256) __nv_bfloat16 g_Qh[N_TOT * DDIM];
__device__ __align__(256) __nv_bfloat16 g_Ql[N_TOT * DDIM];
__device__ __align__(256) __nv_bfloat16 g_Kh[N_TOT * DDIM];
__device__ __align__(256) __nv_bfloat16 g_Kl[N_TOT * DDIM];
__device__ float g_diag[N_TOT];
__device__ float g_m[N_TOT * NSLOT];
__device__ float g_s[N_TOT * NSLOT];

// ---------------- PTX helpers ----------------
__device__ __forceinline__ uint32_t smem_u32(const void* p) {
    uint32_t a;
    asm("{ .reg .u64 t; cvta.to.shared.u64 t, %1; cvt.u32.u64 %0, t; }"
        : "=r"(a) : "l"(p));
    return a;
}
__device__ __forceinline__ void cp16(uint32_t dst, const void* src) {
    asm volatile("cp.async.cg.shared.global [%0], [%1], 16;"
                 :: "r"(dst), "l"(src) : "memory");
}
__device__ __forceinline__ void cp_commit() {
    asm volatile("cp.async.commit_group;" ::: "memory");
}
template <int N>
__device__ __forceinline__ void cp_wait() {
    asm volatile("cp.async.wait_group %0;" :: "n"(N) : "memory");
}
__device__ __forceinline__ void pair_bar(int id) {
    asm volatile("bar.sync %0, 64;" :: "r"(id) : "memory");
}
__device__ __forceinline__ void ldsm4(uint32_t* r, uint32_t addr) {
    asm volatile("ldmatrix.sync.aligned.m8n8.x4.shared.b16 {%0,%1,%2,%3}, [%4];"
                 : "=r"(r[0]), "=r"(r[1]), "=r"(r[2]), "=r"(r[3]) : "r"(addr));
}
__device__ __forceinline__ void mma16816(float* d, const uint32_t* a, const uint32_t* b) {
    asm volatile(
        "mma.sync.aligned.m16n8k16.row.col.f32.bf16.bf16.f32 "
        "{%0,%1,%2,%3}, {%4,%5,%6,%7}, {%8,%9}, {%0,%1,%2,%3};"
        : "+f"(d[0]), "+f"(d[1]), "+f"(d[2]), "+f"(d[3])
        : "r"(a[0]), "r"(a[1]), "r"(a[2]), "r"(a[3]), "r"(b[0]), "r"(b[1]));
}
__device__ __forceinline__ float ex2f(float x) {
    float y;
    asm("ex2.approx.ftz.f32 %0, %1;" : "=f"(y) : "f"(x));
    return y;
}
// packed fp16x2 exp2: two exponentials per MUFU instruction
__device__ __forceinline__ __half2 h2ex2(__half2 x) {
    __half2 y;
    asm("ex2.approx.f16x2 %0, %1;"
        : "=r"(*(uint32_t*)&y) : "r"(*(const uint32_t*)&x));
    return y;
}

// ---------------------------------------------------------------------
// Kernel 1: prep — bf16 hi/lo split (Q scaled by inv_t*log2e) + exact
// fp32 diagonal dot. 256 threads / block, 4 rows per block.
// ---------------------------------------------------------------------
__global__ void __launch_bounds__(256)
prep_kernel(const float* __restrict__ Q, const float* __restrict__ K) {
    const int row = blockIdx.x * 4 + (threadIdx.x >> 6);
    const int lt = threadIdx.x & 63;      // 0..63, 4 elems each

    float4 q4 = ((const float4*)(Q + (size_t)row * DDIM))[lt];
    float4 k4 = ((const float4*)(K + (size_t)row * DDIM))[lt];

    float dot = q4.x * k4.x + q4.y * k4.y + q4.z * k4.z + q4.w * k4.w;

    float qs[4] = {q4.x * QSCALE_F, q4.y * QSCALE_F, q4.z * QSCALE_F, q4.w * QSCALE_F};
    float kv[4] = {k4.x, k4.y, k4.z, k4.w};
    __nv_bfloat16 qh[4], ql[4], kh[4], kl[4];
#pragma unroll
    for (int i = 0; i < 4; i++) {
        qh[i] = __float2bfloat16(qs[i]);
        ql[i] = __float2bfloat16(qs[i] - __bfloat162float(qh[i]));
        kh[i] = __float2bfloat16(kv[i]);
        kl[i] = __float2bfloat16(kv[i] - __bfloat162float(kh[i]));
    }
    size_t b2 = (size_t)row * (DDIM / 2) + lt * 2;
    ((__nv_bfloat162*)g_Qh)[b2]     = __halves2bfloat162(qh[0], qh[1]);
    ((__nv_bfloat162*)g_Qh)[b2 + 1] = __halves2bfloat162(qh[2], qh[3]);
    ((__nv_bfloat162*)g_Ql)[b2]     = __halves2bfloat162(ql[0], ql[1]);
    ((__nv_bfloat162*)g_Ql)[b2 + 1] = __halves2bfloat162(ql[2], ql[3]);
    ((__nv_bfloat162*)g_Kh)[b2]     = __halves2bfloat162(kh[0], kh[1]);
    ((__nv_bfloat162*)g_Kh)[b2 + 1] = __halves2bfloat162(kh[2], kh[3]);
    ((__nv_bfloat162*)g_Kl)[b2]     = __halves2bfloat162(kl[0], kl[1]);
    ((__nv_bfloat162*)g_Kl)[b2 + 1] = __halves2bfloat162(kl[2], kl[3]);

#pragma unroll
    for (int o = 16; o > 0; o >>= 1)
        dot += __shfl_xor_sync(0xffffffffu, dot, o);
    __shared__ float red[8];
    const int wid = threadIdx.x >> 5;
    if ((threadIdx.x & 31) == 0) red[wid] = dot;
    __syncthreads();
    if ((threadIdx.x & 63) == 0)
        g_diag[row] = red[wid] + red[wid + 1];
}

// ---------------------------------------------------------------------
// Kernel 2: persistent mma.sync bf16 GEMM + per-tile softmax partials.
// grid = #SMs. 256 threads = 8 warps, grid 2(M)x4(N), warp tile 64x64.
// Pairwise B ownership + stagger (see R13).
// SMEM: A = Qh|Ql [128x256] (128KB), B 3-stage ring (3x32KB).
// ---------------------------------------------------------------------
#define NSTAGE    3
#define A_BYTES   (2 * 128 * 512)          // 131072
#define B_STAGE   (256 * 128)              // 32768
#define SMEM_DYN  (512 + A_BYTES + NSTAGE * B_STAGE)

__global__ void __launch_bounds__(256, 1)
gemm_lse_kernel(int ncta) {
    extern __shared__ char dsm[];
    const uint32_t base = (smem_u32(dsm) + 127u) & ~127u;
    const uint32_t A0 = base;                    // Qh [128][256], then Ql
    const uint32_t B0 = base + A_BYTES;          // NSTAGE stages

    const int tid = threadIdx.x;
    const int wid = tid >> 5, lane = tid & 31;
    const int warp_m = wid & 1;                  // 0..1 (rows of 64)
    const int warp_n = wid >> 1;                 // 0..3 (cols of 64)
    const int pair = warp_n;
    const int tp = tid & 63;

    const int ustart = (blockIdx.x * UNITS) / ncta;
    const int uendall = ((blockIdx.x + 1) * UNITS) / ncta;

    // ---- per-thread B load descriptors: pair's 64-col slice, 8 x 16B ----
    uint32_t bsrcoff[8], bdst[8];
#pragma unroll
    for (int ii = 0; ii < 8; ii++) {
        int idx = ii * 64 + tp;                 // 0..511 within slice
        int nB = pair * 64 + (idx >> 3);
        int kc = idx & 7;
        bsrcoff[ii] = (uint32_t)(nB * DDIM + kc * 8);
        bdst[ii] = (uint32_t)(nB * 128 + ((kc ^ (nB & 7)) << 4));
    }

    // ---- compute-side address precompute ----
    int rowA[4], rswA[4];
#pragma unroll
    for (int mi = 0; mi < 4; mi++) {
        rowA[mi] = warp_m * 64 + mi * 16 + (lane & 7) + ((lane & 8) ? 8 : 0);
        rswA[mi] = rowA[mi] & 7;
    }
    const int khalf = (lane >> 4) & 1;
    const int hhB = (lane >> 3) & 1;
    uint32_t bOff[4]; int bsw[4];
#pragma unroll
    for (int gp = 0; gp < 4; gp++) {
        int gg = 2 * gp + ((lane >> 4) & 1);
        int nB = warp_n * 64 + gg * 8 + (lane & 7);
        bOff[gp] = (uint32_t)(nB * 128);
        bsw[gp] = nB & 7;
    }

    float acc[4][8][4];
#pragma unroll
    for (int mi = 0; mi < 4; mi++)
#pragma unroll
        for (int g = 0; g < 8; g++)
#pragma unroll
            for (int v = 0; v < 4; v++) acc[mi][g][v] = 0.f;

    for (int u0 = ustart; u0 < uendall; ) {
        const int rt = u0 >> 5;                  // rowtile
        const int u1 = min(uendall, (rt + 1) << 5);
        const int rowBase = rt << 7;
        const int nch = (u1 - u0) * CHUNKS_PT;

        // ---- load A (Qh,Ql rows rowBase..+127), swizzled ----
        for (int ii = 0; ii < 32; ii++) {
            int idx = ii * 256 + tid;           // 0..8191 16B-chunks
            int half = idx >> 12;
            int rest = idx & 4095;
            int row = rest >> 5, kc = rest & 31;
            const __nv_bfloat16* src =
                (half ? g_Ql : g_Qh) + (size_t)(rowBase + row) * DDIM + kc * 8;
            cp16(A0 + half * 65536 + row * 512 +
                 (((uint32_t)(kc ^ (row & 7))) << 4), src);
        }
        cp_commit();   // group: A

        auto loadB = [&](int gc) {
            int unit = u0 + gc / CHUNKS_PT;
            int sub = gc % CHUNKS_PT;
            int ctile = unit & 31;
            int kc4 = sub >> 1, h = sub & 1;    // h=0: Kh, h=1: Kl
            const __nv_bfloat16* bsrc = h ? g_Kl : g_Kh;
            const __nv_bfloat16* srow =
                bsrc + (size_t)(ctile * 256) * DDIM + kc4 * 64;
            uint32_t dstB = B0 + (uint32_t)(gc % NSTAGE) * B_STAGE;
#pragma unroll
            for (int ii = 0; ii < 8; ii++)
                cp16(dstB + bdst[ii], srow + bsrcoff[ii]);
        };

        loadB(0); cp_commit();
        loadB(1); cp_commit();
        cp_wait<0>();
        __syncthreads();     // A + B0,B1 resident for everyone

        // ---- stagger: seed inter-pair drift so epilogues de-align ----
        if (pair != 0) {
            unsigned long long t0 = clock64();
            unsigned long long dl = (unsigned long long)(pair * 800);
            while (clock64() - t0 < dl) { }
        }

        for (int c = 0; c < nch; c++) {
            cp_wait<1>();            // own slice of B(c) resident
            pair_bar(pair + 1);      // partner done with chunk c-1

            if (c + 2 < nch) loadB(c + 2);
            cp_commit();             // unconditional: keeps wait<1> exact

            const int sub = c % CHUNKS_PT;
            const int kc4 = sub >> 1, h = sub & 1;
            const uint32_t Bst = B0 + (uint32_t)(c % NSTAGE) * B_STAGE;

#pragma unroll
            for (int ks = 0; ks < 4; ks++) {
                const int k0c = (kc4 * 64 + ks * 16) >> 3;   // even
                const uint32_t ach = (uint32_t)(k0c | khalf);
                uint32_t a1[4][4], a2[4][4];
#pragma unroll
                for (int mi = 0; mi < 4; mi++)
                    ldsm4(a1[mi], A0 + (uint32_t)rowA[mi] * 512 +
                                  (((ach ^ (uint32_t)rswA[mi])) << 4));
                if (h == 0) {
#pragma unroll
                    for (int mi = 0; mi < 4; mi++)
                        ldsm4(a2[mi], A0 + 65536u + (uint32_t)rowA[mi] * 512 +
                                      (((ach ^ (uint32_t)rswA[mi])) << 4));
                }
                uint32_t b[8][2];
#pragma unroll
                for (int gp = 0; gp < 4; gp++) {
                    uint32_t t4[4];
                    uint32_t ch = (uint32_t)(ks * 2 + hhB);
                    ldsm4(t4, Bst + bOff[gp] + ((ch ^ (uint32_t)bsw[gp]) << 4));
                    b[2 * gp][0] = t4[0]; b[2 * gp][1] = t4[1];
                    b[2 * gp + 1][0] = t4[2]; b[2 * gp + 1][1] = t4[3];
                }
                // pass 1: Qh x B
#pragma unroll
                for (int mi = 0; mi < 4; mi++)
#pragma unroll
                    for (int g = 0; g < 8; g++)
                        mma16816(acc[mi][g], a1[mi], b[g]);
                // pass 2 (Kh chunks only): Ql x B, reusing b frags
                if (h == 0) {
#pragma unroll
                    for (int mi = 0; mi < 4; mi++)
#pragma unroll
                        for (int g = 0; g < 8; g++)
                            mma16816(acc[mi][g], a2[mi], b[g]);
                }
            }

            if (sub == CHUNKS_PT - 1) {
                // ---- per-tile softmax partial (packed fp16x2 exp2) ----
                const int unit = u0 + c / CHUNKS_PT;
                const int slot = (unit & 31) * 4 + warp_n;
#pragma unroll
                for (int mi = 0; mi < 4; mi++) {
#pragma unroll
                    for (int p = 0; p < 2; p++) {
                        float rm = acc[mi][0][2 * p];
#pragma unroll
                        for (int g = 0; g < 8; g++) {
                            rm = fmaxf(rm, acc[mi][g][2 * p]);
                            rm = fmaxf(rm, acc[mi][g][2 * p + 1]);
                        }
                        rm = fmaxf(rm, __shfl_xor_sync(0xffffffffu, rm, 1));
                        rm = fmaxf(rm, __shfl_xor_sync(0xffffffffu, rm, 2));
                        // 8 pairs -> 8 packed exp2 on MUFU, fp16x2 accum
                        __half2 hs = __floats2half2_rn(0.f, 0.f);
#pragma unroll
                        for (int g = 0; g < 8; g++) {
                            __half2 hx = __floats2half2_rn(
                                acc[mi][g][2 * p] - rm,
                                acc[mi][g][2 * p + 1] - rm);
                            hs = __hadd2(hs, h2ex2(hx));
                        }
                        float2 fs = __half22float2(hs);
                        float ssum = fs.x + fs.y;
                        ssum += __shfl_xor_sync(0xffffffffu, ssum, 1);
                        ssum += __shfl_xor_sync(0xffffffffu, ssum, 2);
                        if ((lane & 3) == 0) {
                            int row = rowBase + warp_m * 64 + mi * 16 +
                                      (lane >> 2) + 8 * p;
                            g_m[row * NSLOT + slot] = rm;
                            g_s[row * NSLOT + slot] = ssum;
                        }
                    }
                }
#pragma unroll
                for (int mi = 0; mi < 4; mi++)
#pragma unroll
                    for (int g = 0; g < 8; g++)
#pragma unroll
                        for (int v = 0; v < 4; v++) acc[mi][g][v] = 0.f;
            }
        }

        cp_wait<0>();
        __syncthreads();     // all pairs done before A overwrite
        u0 = u1;
    }
}

// ---------------------------------------------------------------------
// Kernel 3: combine 128 partials per row into the loss. 1 warp / row.
// ---------------------------------------------------------------------
__global__ void __launch_bounds__(256)
combine_kernel(float* __restrict__ out) {
    int row = (blockIdx.x * blockDim.x + threadIdx.x) >> 5;
    int lane = threadIdx.x & 31;
    if (row >= N_TOT) return;

    float4 mv = ((const float4*)(g_m + (size_t)row * NSLOT))[lane];
    float4 sv = ((const float4*)(g_s + (size_t)row * NSLOT))[lane];

    float M = fmaxf(fmaxf(mv.x, mv.y), fmaxf(mv.z, mv.w));
#pragma unroll
    for (int o = 16; o > 0; o >>= 1)
        M = fmaxf(M, __shfl_xor_sync(0xffffffffu, M, o));

    float S = sv.x * ex2f(mv.x - M) + sv.y * ex2f(mv.y - M) +
              sv.z * ex2f(mv.z - M) + sv.w * ex2f(mv.w - M);
#pragma unroll
    for (int o = 16; o > 0; o >>= 1)
        S += __shfl_xor_sync(0xffffffffu, S, o);

    if (lane == 0)
        out[row] = LN2_F * (M + log2f(S)) - INV_T_F * g_diag[row];
}

// ---------------------------------------------------------------------
extern "C" void kernel_launch(void* const* d_in, const int* in_sizes, int n_in,
                              void* d_out, int out_size) {
    const float* Q = (const float*)d_in[0];
    const float* K = (const float*)d_in[1];
    float* out = (float*)d_out;

    cudaFuncSetAttribute(gemm_lse_kernel,
                         cudaFuncAttributeMaxDynamicSharedMemorySize, SMEM_DYN);

    int nsm = 148;
    cudaDeviceGetAttribute(&nsm, cudaDevAttrMultiProcessorCount, 0);
    if (nsm < 8) nsm = 148;
    if (nsm > 512) nsm = 512;

    prep_kernel<<<N_TOT / 4, 256>>>(Q, K);
    gemm_lse_kernel<<<nsm, 256, SMEM_DYN>>>(nsm);
    combine_kernel<<<N_TOT * 32 / 256, 256>>>(out);
}

// round 15
// speedup vs baseline: 2.3445x; 2.3445x over previous
#include <cuda_runtime.h>
#include <cuda_fp16.h>
#include <stdint.h>

// =====================================================================
// PatchNCELoss: loss[r] = lse_c( inv_t * q[r]·k[c] ) - inv_t * q[r]·k[r]
// Q,K: [8192, 256] fp32.
// R15: SINGLE fp16 product GEMM (q pre-scaled by inv_t*log2e, k in
// fp16; 11-bit mantissa => per-logit err ~0.1 nats, loss rel_err
// ~1e-4, 7-10x under threshold).  3x fewer HMMA than the bf16 hi/lo
// 3-product core.  Exact fp32 diagonal.  Persistent 148-CTA schedule,
// pairwise sync, pair stagger, per-tile log2-domain softmax partials.
// =====================================================================

#define N_TOT 8192
#define DDIM  256
#define INV_T_F     14.285714285714286f
#define QSCALE_F    20.609929155556627f   /* inv_t * log2(e) */
#define LN2_F       0.6931471805599453f

#define COLTILES  32                       // 256-col tiles
#define UNITS     (64 * COLTILES)          // 2048
#define CHUNKS_PT 4                        // 4 k64 chunks, single pass
#define NSLOT     128                      // 32 coltiles x 4 warp_n

// ---- device scratch ----
__device__ __align__(256) __half g_Qh[N_TOT * DDIM];
__device__ __align__(256) __half g_Kh[N_TOT * DDIM];
__device__ float g_diag[N_TOT];
__device__ float g_m[N_TOT * NSLOT];
__device__ float g_s[N_TOT * NSLOT];

// ---------------- PTX helpers ----------------
__device__ __forceinline__ uint32_t smem_u32(const void* p) {
    uint32_t a;
    asm("{ .reg .u64 t; cvta.to.shared.u64 t, %1; cvt.u32.u64 %0, t; }"
        : "=r"(a) : "l"(p));
    return a;
}
__device__ __forceinline__ void cp16(uint32_t dst, const void* src) {
    asm volatile("cp.async.cg.shared.global [%0], [%1], 16;"
                 :: "r"(dst), "l"(src) : "memory");
}
__device__ __forceinline__ void cp_commit() {
    asm volatile("cp.async.commit_group;" ::: "memory");
}
template <int N>
__device__ __forceinline__ void cp_wait() {
    asm volatile("cp.async.wait_group %0;" :: "n"(N) : "memory");
}
__device__ __forceinline__ void pair_bar(int id) {
    asm volatile("bar.sync %0, 64;" :: "r"(id) : "memory");
}
__device__ __forceinline__ void ldsm4(uint32_t* r, uint32_t addr) {
    asm volatile("ldmatrix.sync.aligned.m8n8.x4.shared.b16 {%0,%1,%2,%3}, [%4];"
                 : "=r"(r[0]), "=r"(r[1]), "=r"(r[2]), "=r"(r[3]) : "r"(addr));
}
// fp16 mma m16n8k16 with fp32 accumulate
__device__ __forceinline__ void mma16816(float* d, const uint32_t* a, const uint32_t* b) {
    asm volatile(
        "mma.sync.aligned.m16n8k16.row.col.f32.f16.f16.f32 "
        "{%0,%1,%2,%3}, {%4,%5,%6,%7}, {%8,%9}, {%0,%1,%2,%3};"
        : "+f"(d[0]), "+f"(d[1]), "+f"(d[2]), "+f"(d[3])
        : "r"(a[0]), "r"(a[1]), "r"(a[2]), "r"(a[3]), "r"(b[0]), "r"(b[1]));
}
__device__ __forceinline__ float ex2f(float x) {
    float y;
    asm("ex2.approx.ftz.f32 %0, %1;" : "=f"(y) : "f"(x));
    return y;
}
__device__ __forceinline__ __half2 h2ex2(__half2 x) {
    __half2 y;
    asm("ex2.approx.f16x2 %0, %1;"
        : "=r"(*(uint32_t*)&y) : "r"(*(const uint32_t*)&x));
    return y;
}

// ---------------------------------------------------------------------
// Kernel 1: prep — fp16 quantization (Q scaled by inv_t*log2e) + exact
// fp32 diagonal dot. 256 threads / block, 4 rows per block.
// ---------------------------------------------------------------------
__global__ void __launch_bounds__(256)
prep_kernel(const float* __restrict__ Q, const float* __restrict__ K) {
    const int row = blockIdx.x * 4 + (threadIdx.x >> 6);
    const int lt = threadIdx.x & 63;      // 0..63, 4 elems each

    float4 q4 = ((const float4*)(Q + (size_t)row * DDIM))[lt];
    float4 k4 = ((const float4*)(K + (size_t)row * DDIM))[lt];

    float dot = q4.x * k4.x + q4.y * k4.y + q4.z * k4.z + q4.w * k4.w;

    size_t b2 = (size_t)row * (DDIM / 2) + lt * 2;
    ((__half2*)g_Qh)[b2]     = __floats2half2_rn(q4.x * QSCALE_F, q4.y * QSCALE_F);
    ((__half2*)g_Qh)[b2 + 1] = __floats2half2_rn(q4.z * QSCALE_F, q4.w * QSCALE_F);
    ((__half2*)g_Kh)[b2]     = __floats2half2_rn(k4.x, k4.y);
    ((__half2*)g_Kh)[b2 + 1] = __floats2half2_rn(k4.z, k4.w);

#pragma unroll
    for (int o = 16; o > 0; o >>= 1)
        dot += __shfl_xor_sync(0xffffffffu, dot, o);
    __shared__ float red[8];
    const int wid = threadIdx.x >> 5;
    if ((threadIdx.x & 31) == 0) red[wid] = dot;
    __syncthreads();
    if ((threadIdx.x & 63) == 0)
        g_diag[row] = red[wid] + red[wid + 1];
}

// ---------------------------------------------------------------------
// Kernel 2: persistent fp16 mma GEMM + per-tile softmax partials.
// grid = #SMs. 256 threads = 8 warps, grid 2(M)x4(N), warp tile 64x64.
// Pair p owns B columns [64p, 64p+64); pair bar + pair stagger.
// SMEM: A = Q fp16 [128x256] (64KB), B 3-stage ring (3x32KB).
// ---------------------------------------------------------------------
#define NSTAGE    3
#define A_BYTES   (128 * 512)              // 65536
#define B_STAGE   (256 * 128)              // 32768
#define SMEM_DYN  (512 + A_BYTES + NSTAGE * B_STAGE)

__global__ void __launch_bounds__(256, 1)
gemm_lse_kernel(int ncta) {
    extern __shared__ char dsm[];
    const uint32_t base = (smem_u32(dsm) + 127u) & ~127u;
    const uint32_t A0 = base;                    // Q [128][512B]
    const uint32_t B0 = base + A_BYTES;          // NSTAGE stages

    const int tid = threadIdx.x;
    const int wid = tid >> 5, lane = tid & 31;
    const int warp_m = wid & 1;                  // 0..1 (rows of 64)
    const int warp_n = wid >> 1;                 // 0..3 (cols of 64)
    const int pair = warp_n;
    const int tp = tid & 63;

    const int ustart = (blockIdx.x * UNITS) / ncta;
    const int uendall = ((blockIdx.x + 1) * UNITS) / ncta;

    // ---- per-thread B load descriptors: pair's 64-col slice, 8 x 16B ----
    uint32_t bsrcoff[8], bdst[8];
#pragma unroll
    for (int ii = 0; ii < 8; ii++) {
        int idx = ii * 64 + tp;                 // 0..511 within slice
        int nB = pair * 64 + (idx >> 3);
        int kc = idx & 7;
        bsrcoff[ii] = (uint32_t)(nB * DDIM + kc * 8);
        bdst[ii] = (uint32_t)(nB * 128 + ((kc ^ (nB & 7)) << 4));
    }

    // ---- compute-side address precompute ----
    int rowA[4], rswA[4];
#pragma unroll
    for (int mi = 0; mi < 4; mi++) {
        rowA[mi] = warp_m * 64 + mi * 16 + (lane & 7) + ((lane & 8) ? 8 : 0);
        rswA[mi] = rowA[mi] & 7;
    }
    const int khalf = (lane >> 4) & 1;
    const int hhB = (lane >> 3) & 1;
    uint32_t bOff[4]; int bsw[4];
#pragma unroll
    for (int gp = 0; gp < 4; gp++) {
        int gg = 2 * gp + ((lane >> 4) & 1);
        int nB = warp_n * 64 + gg * 8 + (lane & 7);
        bOff[gp] = (uint32_t)(nB * 128);
        bsw[gp] = nB & 7;
    }

    float acc[4][8][4];
#pragma unroll
    for (int mi = 0; mi < 4; mi++)
#pragma unroll
        for (int g = 0; g < 8; g++)
#pragma unroll
            for (int v = 0; v < 4; v++) acc[mi][g][v] = 0.f;

    for (int u0 = ustart; u0 < uendall; ) {
        const int rt = u0 >> 5;                  // rowtile
        const int u1 = min(uendall, (rt + 1) << 5);
        const int rowBase = rt << 7;
        const int nch = (u1 - u0) * CHUNKS_PT;

        // ---- load A (Q rows rowBase..+127), swizzled: 4096 x 16B ----
        for (int ii = 0; ii < 16; ii++) {
            int idx = ii * 256 + tid;           // 0..4095
            int row = idx >> 5, kc = idx & 31;
            const __half* src =
                g_Qh + (size_t)(rowBase + row) * DDIM + kc * 8;
            cp16(A0 + row * 512 + (((uint32_t)(kc ^ (row & 7))) << 4), src);
        }
        cp_commit();   // group: A

        auto loadB = [&](int gc) {
            int unit = u0 + gc / CHUNKS_PT;
            int kc4 = gc % CHUNKS_PT;
            int ctile = unit & 31;
            const __half* srow =
                g_Kh + (size_t)(ctile * 256) * DDIM + kc4 * 64;
            uint32_t dstB = B0 + (uint32_t)(gc % NSTAGE) * B_STAGE;
#pragma unroll
            for (int ii = 0; ii < 8; ii++)
                cp16(dstB + bdst[ii], srow + bsrcoff[ii]);
        };

        loadB(0); cp_commit();
        loadB(1); cp_commit();
        cp_wait<0>();
        __syncthreads();     // A + B0,B1 resident for everyone

        // ---- stagger: seed inter-pair drift so epilogues de-align ----
        if (pair != 0) {
            unsigned long long t0 = clock64();
            unsigned long long dl = (unsigned long long)(pair * 800);
            while (clock64() - t0 < dl) { }
        }

        for (int c = 0; c < nch; c++) {
            cp_wait<1>();            // own slice of B(c) resident
            pair_bar(pair + 1);      // partner done with chunk c-1

            if (c + 2 < nch) loadB(c + 2);
            cp_commit();             // unconditional: keeps wait<1> exact

            const int kc4 = c % CHUNKS_PT;
            const uint32_t Bst = B0 + (uint32_t)(c % NSTAGE) * B_STAGE;

#pragma unroll
            for (int ks = 0; ks < 4; ks++) {
                const int k0c = (kc4 * 64 + ks * 16) >> 3;   // even
                const uint32_t ach = (uint32_t)(k0c | khalf);
                uint32_t a1[4][4];
#pragma unroll
                for (int mi = 0; mi < 4; mi++)
                    ldsm4(a1[mi], A0 + (uint32_t)rowA[mi] * 512 +
                                  (((ach ^ (uint32_t)rswA[mi])) << 4));
                uint32_t b[8][2];
#pragma unroll
                for (int gp = 0; gp < 4; gp++) {
                    uint32_t t4[4];
                    uint32_t ch = (uint32_t)(ks * 2 + hhB);
                    ldsm4(t4, Bst + bOff[gp] + ((ch ^ (uint32_t)bsw[gp]) << 4));
                    b[2 * gp][0] = t4[0]; b[2 * gp][1] = t4[1];
                    b[2 * gp + 1][0] = t4[2]; b[2 * gp + 1][1] = t4[3];
                }
#pragma unroll
                for (int mi = 0; mi < 4; mi++)
#pragma unroll
                    for (int g = 0; g < 8; g++)
                        mma16816(acc[mi][g], a1[mi], b[g]);
            }

            if (kc4 == CHUNKS_PT - 1) {
                // ---- per-tile softmax partial (packed fp16x2 exp2) ----
                const int unit = u0 + c / CHUNKS_PT;
                const int slot = (unit & 31) * 4 + warp_n;
#pragma unroll
                for (int mi = 0; mi < 4; mi++) {
#pragma unroll
                    for (int p = 0; p < 2; p++) {
                        float rm = acc[mi][0][2 * p];
#pragma unroll
                        for (int g = 0; g < 8; g++) {
                            rm = fmaxf(rm, acc[mi][g][2 * p]);
                            rm = fmaxf(rm, acc[mi][g][2 * p + 1]);
                        }
                        rm = fmaxf(rm, __shfl_xor_sync(0xffffffffu, rm, 1));
                        rm = fmaxf(rm, __shfl_xor_sync(0xffffffffu, rm, 2));
                        __half2 hs = __floats2half2_rn(0.f, 0.f);
#pragma unroll
                        for (int g = 0; g < 8; g++) {
                            __half2 hx = __floats2half2_rn(
                                acc[mi][g][2 * p] - rm,
                                acc[mi][g][2 * p + 1] - rm);
                            hs = __hadd2(hs, h2ex2(hx));
                        }
                        float2 fs = __half22float2(hs);
                        float ssum = fs.x + fs.y;
                        ssum += __shfl_xor_sync(0xffffffffu, ssum, 1);
                        ssum += __shfl_xor_sync(0xffffffffu, ssum, 2);
                        if ((lane & 3) == 0) {
                            int row = rowBase + warp_m * 64 + mi * 16 +
                                      (lane >> 2) + 8 * p;
                            g_m[row * NSLOT + slot] = rm;
                            g_s[row * NSLOT + slot] = ssum;
                        }
                    }
                }
#pragma unroll
                for (int mi = 0; mi < 4; mi++)
#pragma unroll
                    for (int g = 0; g < 8; g++)
#pragma unroll
                        for (int v = 0; v < 4; v++) acc[mi][g][v] = 0.f;
            }
        }

        cp_wait<0>();
        __syncthreads();     // all pairs done before A overwrite
        u0 = u1;
    }
}

// ---------------------------------------------------------------------
// Kernel 3: combine 128 partials per row into the loss. 1 warp / row.
// ---------------------------------------------------------------------
__global__ void __launch_bounds__(256)
combine_kernel(float* __restrict__ out) {
    int row = (blockIdx.x * blockDim.x + threadIdx.x) >> 5;
    int lane = threadIdx.x & 31;
    if (row >= N_TOT) return;

    float4 mv = ((const float4*)(g_m + (size_t)row * NSLOT))[lane];
    float4 sv = ((const float4*)(g_s + (size_t)row * NSLOT))[lane];

    float M = fmaxf(fmaxf(mv.x, mv.y), fmaxf(mv.z, mv.w));
#pragma unroll
    for (int o = 16; o > 0; o >>= 1)
        M = fmaxf(M, __shfl_xor_sync(0xffffffffu, M, o));

    float S = sv.x * ex2f(mv.x - M) + sv.y * ex2f(mv.y - M) +
              sv.z * ex2f(mv.z - M) + sv.w * ex2f(mv.w - M);
#pragma unroll
    for (int o = 16; o > 0; o >>= 1)
        S += __shfl_xor_sync(0xffffffffu, S, o);

    if (lane == 0)
        out[row] = LN2_F * (M + log2f(S)) - INV_T_F * g_diag[row];
}

// ---------------------------------------------------------------------
extern "C" void kernel_launch(void* const* d_in, const int* in_sizes, int n_in,
                              void* d_out, int out_size) {
    const float* Q = (const float*)d_in[0];
    const float* K = (const float*)d_in[1];
    float* out = (float*)d_out;

    cudaFuncSetAttribute(gemm_lse_kernel,
                         cudaFuncAttributeMaxDynamicSharedMemorySize, SMEM_DYN);

    int nsm = 148;
    cudaDeviceGetAttribute(&nsm, cudaDevAttrMultiProcessorCount, 0);
    if (nsm < 8) nsm = 148;
    if (nsm > 512) nsm = 512;

    prep_kernel<<<N_TOT / 4, 256>>>(Q, K);
    gemm_lse_kernel<<<nsm, 256, SMEM_DYN>>>(nsm);
    combine_kernel<<<N_TOT * 32 / 256, 256>>>(out);
}

// round 16
// speedup vs baseline: 2.4403x; 1.0409x over previous
#include <cuda_runtime.h>
#include <cuda_fp16.h>
#include <stdint.h>

// =====================================================================
// PatchNCELoss: loss[r] = lse_c( inv_t * q[r]·k[c] ) - inv_t * q[r]·k[r]
// Q,K: [8192, 256] fp32.
// R16: single fp16-product GEMM (R15 core).  Tuning: stagger once per
// CTA, 4-stage B ring with prefetch distance 3, single block barrier
// per rowtile.  Exact fp32 diagonal; per-tile log2 softmax partials.
// =====================================================================

#define N_TOT 8192
#define DDIM  256
#define INV_T_F     14.285714285714286f
#define QSCALE_F    20.609929155556627f   /* inv_t * log2(e) */
#define LN2_F       0.6931471805599453f

#define COLTILES  32                       // 256-col tiles
#define UNITS     (64 * COLTILES)          // 2048
#define CHUNKS_PT 4                        // 4 k64 chunks, single pass
#define NSLOT     128                      // 32 coltiles x 4 warp_n

// ---- device scratch ----
__device__ __align__(256) __half g_Qh[N_TOT * DDIM];
__device__ __align__(256) __half g_Kh[N_TOT * DDIM];
__device__ float g_diag[N_TOT];
__device__ float g_m[N_TOT * NSLOT];
__device__ float g_s[N_TOT * NSLOT];

// ---------------- PTX helpers ----------------
__device__ __forceinline__ uint32_t smem_u32(const void* p) {
    uint32_t a;
    asm("{ .reg .u64 t; cvta.to.shared.u64 t, %1; cvt.u32.u64 %0, t; }"
        : "=r"(a) : "l"(p));
    return a;
}
__device__ __forceinline__ void cp16(uint32_t dst, const void* src) {
    asm volatile("cp.async.cg.shared.global [%0], [%1], 16;"
                 :: "r"(dst), "l"(src) : "memory");
}
__device__ __forceinline__ void cp_commit() {
    asm volatile("cp.async.commit_group;" ::: "memory");
}
template <int N>
__device__ __forceinline__ void cp_wait() {
    asm volatile("cp.async.wait_group %0;" :: "n"(N) : "memory");
}
__device__ __forceinline__ void pair_bar(int id) {
    asm volatile("bar.sync %0, 64;" :: "r"(id) : "memory");
}
__device__ __forceinline__ void ldsm4(uint32_t* r, uint32_t addr) {
    asm volatile("ldmatrix.sync.aligned.m8n8.x4.shared.b16 {%0,%1,%2,%3}, [%4];"
                 : "=r"(r[0]), "=r"(r[1]), "=r"(r[2]), "=r"(r[3]) : "r"(addr));
}
// fp16 mma m16n8k16 with fp32 accumulate
__device__ __forceinline__ void mma16816(float* d, const uint32_t* a, const uint32_t* b) {
    asm volatile(
        "mma.sync.aligned.m16n8k16.row.col.f32.f16.f16.f32 "
        "{%0,%1,%2,%3}, {%4,%5,%6,%7}, {%8,%9}, {%0,%1,%2,%3};"
        : "+f"(d[0]), "+f"(d[1]), "+f"(d[2]), "+f"(d[3])
        : "r"(a[0]), "r"(a[1]), "r"(a[2]), "r"(a[3]), "r"(b[0]), "r"(b[1]));
}
__device__ __forceinline__ float ex2f(float x) {
    float y;
    asm("ex2.approx.ftz.f32 %0, %1;" : "=f"(y) : "f"(x));
    return y;
}
__device__ __forceinline__ __half2 h2ex2(__half2 x) {
    __half2 y;
    asm("ex2.approx.f16x2 %0, %1;"
        : "=r"(*(uint32_t*)&y) : "r"(*(const uint32_t*)&x));
    return y;
}

// ---------------------------------------------------------------------
// Kernel 1: prep — fp16 quantization (Q scaled by inv_t*log2e) + exact
// fp32 diagonal dot. 256 threads / block, 4 rows per block.
// ---------------------------------------------------------------------
__global__ void __launch_bounds__(256)
prep_kernel(const float* __restrict__ Q, const float* __restrict__ K) {
    const int row = blockIdx.x * 4 + (threadIdx.x >> 6);
    const int lt = threadIdx.x & 63;      // 0..63, 4 elems each

    float4 q4 = ((const float4*)(Q + (size_t)row * DDIM))[lt];
    float4 k4 = ((const float4*)(K + (size_t)row * DDIM))[lt];

    float dot = q4.x * k4.x + q4.y * k4.y + q4.z * k4.z + q4.w * k4.w;

    size_t b2 = (size_t)row * (DDIM / 2) + lt * 2;
    ((__half2*)g_Qh)[b2]     = __floats2half2_rn(q4.x * QSCALE_F, q4.y * QSCALE_F);
    ((__half2*)g_Qh)[b2 + 1] = __floats2half2_rn(q4.z * QSCALE_F, q4.w * QSCALE_F);
    ((__half2*)g_Kh)[b2]     = __floats2half2_rn(k4.x, k4.y);
    ((__half2*)g_Kh)[b2 + 1] = __floats2half2_rn(k4.z, k4.w);

#pragma unroll
    for (int o = 16; o > 0; o >>= 1)
        dot += __shfl_xor_sync(0xffffffffu, dot, o);
    __shared__ float red[8];
    const int wid = threadIdx.x >> 5;
    if ((threadIdx.x & 31) == 0) red[wid] = dot;
    __syncthreads();
    if ((threadIdx.x & 63) == 0)
        g_diag[row] = red[wid] + red[wid + 1];
}

// ---------------------------------------------------------------------
// Kernel 2: persistent fp16 mma GEMM + per-tile softmax partials.
// grid = #SMs. 256 threads = 8 warps, grid 2(M)x4(N), warp tile 64x64.
// Pair p owns B columns [64p, 64p+64); pair bar; stagger once per CTA.
// SMEM: A = Q fp16 [128x256] (64KB), B 4-stage ring (4x32KB).
// ---------------------------------------------------------------------
#define NSTAGE    4
#define A_BYTES   (128 * 512)              // 65536
#define B_STAGE   (256 * 128)              // 32768
#define SMEM_DYN  (512 + A_BYTES + NSTAGE * B_STAGE)

__global__ void __launch_bounds__(256, 1)
gemm_lse_kernel(int ncta) {
    extern __shared__ char dsm[];
    const uint32_t base = (smem_u32(dsm) + 127u) & ~127u;
    const uint32_t A0 = base;                    // Q [128][512B]
    const uint32_t B0 = base + A_BYTES;          // NSTAGE stages

    const int tid = threadIdx.x;
    const int wid = tid >> 5, lane = tid & 31;
    const int warp_m = wid & 1;                  // 0..1 (rows of 64)
    const int warp_n = wid >> 1;                 // 0..3 (cols of 64)
    const int pair = warp_n;
    const int tp = tid & 63;

    const int ustart = (blockIdx.x * UNITS) / ncta;
    const int uendall = ((blockIdx.x + 1) * UNITS) / ncta;

    // ---- per-thread B load descriptors: pair's 64-col slice, 8 x 16B ----
    uint32_t bsrcoff[8], bdst[8];
#pragma unroll
    for (int ii = 0; ii < 8; ii++) {
        int idx = ii * 64 + tp;                 // 0..511 within slice
        int nB = pair * 64 + (idx >> 3);
        int kc = idx & 7;
        bsrcoff[ii] = (uint32_t)(nB * DDIM + kc * 8);
        bdst[ii] = (uint32_t)(nB * 128 + ((kc ^ (nB & 7)) << 4));
    }

    // ---- compute-side address precompute ----
    int rowA[4], rswA[4];
#pragma unroll
    for (int mi = 0; mi < 4; mi++) {
        rowA[mi] = warp_m * 64 + mi * 16 + (lane & 7) + ((lane & 8) ? 8 : 0);
        rswA[mi] = rowA[mi] & 7;
    }
    const int khalf = (lane >> 4) & 1;
    const int hhB = (lane >> 3) & 1;
    uint32_t bOff[4]; int bsw[4];
#pragma unroll
    for (int gp = 0; gp < 4; gp++) {
        int gg = 2 * gp + ((lane >> 4) & 1);
        int nB = warp_n * 64 + gg * 8 + (lane & 7);
        bOff[gp] = (uint32_t)(nB * 128);
        bsw[gp] = nB & 7;
    }

    float acc[4][8][4];
#pragma unroll
    for (int mi = 0; mi < 4; mi++)
#pragma unroll
        for (int g = 0; g < 8; g++)
#pragma unroll
            for (int v = 0; v < 4; v++) acc[mi][g][v] = 0.f;

    bool staggered = false;

    for (int u0 = ustart; u0 < uendall; ) {
        const int rt = u0 >> 5;                  // rowtile
        const int u1 = min(uendall, (rt + 1) << 5);
        const int rowBase = rt << 7;
        const int nch = (u1 - u0) * CHUNKS_PT;

        // ---- load A (Q rows rowBase..+127), swizzled: 4096 x 16B ----
        for (int ii = 0; ii < 16; ii++) {
            int idx = ii * 256 + tid;           // 0..4095
            int row = idx >> 5, kc = idx & 31;
            const __half* src =
                g_Qh + (size_t)(rowBase + row) * DDIM + kc * 8;
            cp16(A0 + row * 512 + (((uint32_t)(kc ^ (row & 7))) << 4), src);
        }
        cp_commit();   // group: A (FIFO-oldest)

        auto loadB = [&](int gc) {
            int unit = u0 + gc / CHUNKS_PT;
            int kc4 = gc % CHUNKS_PT;
            int ctile = unit & 31;
            const __half* srow =
                g_Kh + (size_t)(ctile * 256) * DDIM + kc4 * 64;
            uint32_t dstB = B0 + (uint32_t)(gc % NSTAGE) * B_STAGE;
#pragma unroll
            for (int ii = 0; ii < 8; ii++)
                cp16(dstB + bdst[ii], srow + bsrcoff[ii]);
        };

        loadB(0); cp_commit();
        loadB(1); cp_commit();
        loadB(2); cp_commit();
        cp_wait<3>();        // A complete (oldest of 4 pending groups)
        __syncthreads();     // A visible to all warps

        // ---- stagger ONCE per CTA: seed inter-pair drift ----
        if (!staggered && pair != 0) {
            unsigned long long t0 = clock64();
            unsigned long long dl = (unsigned long long)(pair * 800);
            while (clock64() - t0 < dl) { }
        }
        staggered = true;

        for (int c = 0; c < nch; c++) {
            cp_wait<2>();            // own slice of B(c) resident
            pair_bar(pair + 1);      // partner done with chunk c-1

            if (c + 3 < nch) loadB(c + 3);
            cp_commit();             // unconditional: keeps wait<2> exact

            const int kc4 = c % CHUNKS_PT;
            const uint32_t Bst = B0 + (uint32_t)(c % NSTAGE) * B_STAGE;

#pragma unroll
            for (int ks = 0; ks < 4; ks++) {
                const int k0c = (kc4 * 64 + ks * 16) >> 3;   // even
                const uint32_t ach = (uint32_t)(k0c | khalf);
                uint32_t a1[4][4];
#pragma unroll
                for (int mi = 0; mi < 4; mi++)
                    ldsm4(a1[mi], A0 + (uint32_t)rowA[mi] * 512 +
                                  (((ach ^ (uint32_t)rswA[mi])) << 4));
                uint32_t b[8][2];
#pragma unroll
                for (int gp = 0; gp < 4; gp++) {
                    uint32_t t4[4];
                    uint32_t ch = (uint32_t)(ks * 2 + hhB);
                    ldsm4(t4, Bst + bOff[gp] + ((ch ^ (uint32_t)bsw[gp]) << 4));
                    b[2 * gp][0] = t4[0]; b[2 * gp][1] = t4[1];
                    b[2 * gp + 1][0] = t4[2]; b[2 * gp + 1][1] = t4[3];
                }
#pragma unroll
                for (int mi = 0; mi < 4; mi++)
#pragma unroll
                    for (int g = 0; g < 8; g++)
                        mma16816(acc[mi][g], a1[mi], b[g]);
            }

            if (kc4 == CHUNKS_PT - 1) {
                // ---- per-tile softmax partial (packed fp16x2 exp2) ----
                const int unit = u0 + c / CHUNKS_PT;
                const int slot = (unit & 31) * 4 + warp_n;
#pragma unroll
                for (int mi = 0; mi < 4; mi++) {
#pragma unroll
                    for (int p = 0; p < 2; p++) {
                        float rm = acc[mi][0][2 * p];
#pragma unroll
                        for (int g = 0; g < 8; g++) {
                            rm = fmaxf(rm, acc[mi][g][2 * p]);
                            rm = fmaxf(rm, acc[mi][g][2 * p + 1]);
                        }
                        rm = fmaxf(rm, __shfl_xor_sync(0xffffffffu, rm, 1));
                        rm = fmaxf(rm, __shfl_xor_sync(0xffffffffu, rm, 2));
                        __half2 hs = __floats2half2_rn(0.f, 0.f);
#pragma unroll
                        for (int g = 0; g < 8; g++) {
                            __half2 hx = __floats2half2_rn(
                                acc[mi][g][2 * p] - rm,
                                acc[mi][g][2 * p + 1] - rm);
                            hs = __hadd2(hs, h2ex2(hx));
                        }
                        float2 fs = __half22float2(hs);
                        float ssum = fs.x + fs.y;
                        ssum += __shfl_xor_sync(0xffffffffu, ssum, 1);
                        ssum += __shfl_xor_sync(0xffffffffu, ssum, 2);
                        if ((lane & 3) == 0) {
                            int row = rowBase + warp_m * 64 + mi * 16 +
                                      (lane >> 2) + 8 * p;
                            g_m[row * NSLOT + slot] = rm;
                            g_s[row * NSLOT + slot] = ssum;
                        }
                    }
                }
#pragma unroll
                for (int mi = 0; mi < 4; mi++)
#pragma unroll
                    for (int g = 0; g < 8; g++)
#pragma unroll
                        for (int v = 0; v < 4; v++) acc[mi][g][v] = 0.f;
            }
        }

        cp_wait<0>();
        __syncthreads();     // all pairs done before A overwrite
        u0 = u1;
    }
}

// ---------------------------------------------------------------------
// Kernel 3: combine 128 partials per row into the loss. 1 warp / row.
// ---------------------------------------------------------------------
__global__ void __launch_bounds__(256)
combine_kernel(float* __restrict__ out) {
    int row = (blockIdx.x * blockDim.x + threadIdx.x) >> 5;
    int lane = threadIdx.x & 31;
    if (row >= N_TOT) return;

    float4 mv = ((const float4*)(g_m + (size_t)row * NSLOT))[lane];
    float4 sv = ((const float4*)(g_s + (size_t)row * NSLOT))[lane];

    float M = fmaxf(fmaxf(mv.x, mv.y), fmaxf(mv.z, mv.w));
#pragma unroll
    for (int o = 16; o > 0; o >>= 1)
        M = fmaxf(M, __shfl_xor_sync(0xffffffffu, M, o));

    float S = sv.x * ex2f(mv.x - M) + sv.y * ex2f(mv.y - M) +
              sv.z * ex2f(mv.z - M) + sv.w * ex2f(mv.w - M);
#pragma unroll
    for (int o = 16; o > 0; o >>= 1)
        S += __shfl_xor_sync(0xffffffffu, S, o);

    if (lane == 0)
        out[row] = LN2_F * (M + log2f(S)) - INV_T_F * g_diag[row];
}

// ---------------------------------------------------------------------
extern "C" void kernel_launch(void* const* d_in, const int* in_sizes, int n_in,
                              void* d_out, int out_size) {
    const float* Q = (const float*)d_in[0];
    const float* K = (const float*)d_in[1];
    float* out = (float*)d_out;

    cudaFuncSetAttribute(gemm_lse_kernel,
                         cudaFuncAttributeMaxDynamicSharedMemorySize, SMEM_DYN);

    int nsm = 148;
    cudaDeviceGetAttribute(&nsm, cudaDevAttrMultiProcessorCount, 0);
    if (nsm < 8) nsm = 148;
    if (nsm > 512) nsm = 512;

    prep_kernel<<<N_TOT / 4, 256>>>(Q, K);
    gemm_lse_kernel<<<nsm, 256, SMEM_DYN>>>(nsm);
    combine_kernel<<<N_TOT * 32 / 256, 256>>>(out);
}